// round 13
// baseline (speedup 1.0000x reference)
#include <cuda_runtime.h>

// Winograd F(2x2,3x3) with constant Laplacian filter == direct 3x3 conv of each
// 4x4 tile; row-separable:
//   row r = (a,b,c,d):  x_r = (-b, -c),  y_r = (4b-a-c, 4c-b-d)
//   O_row0 = x_0 + y_1 + x_2 ;  O_row1 = x_1 + y_2 + x_3
//
// One lane per input row (float4, coalesced LDG.128); 4-lane groups assemble a
// tile via SHFL. ITERS=4 independent front-batched loads (MLP=4, regs ~32,
// occ ~80%), streaming cache hints. This is the repeatedly-best wall config
// (49.9 / 49.6 us); this round only trims ALU: load guards replaced by index
// clamp (safe — out-of-range values discarded by the store guard), store
// indexing folded to one IMAD per iteration.

#define ITERS 4

__global__ __launch_bounds__(256) void winograd_kernel(
    const float4* __restrict__ in4,   // n4 float4s (4 per tile, row-major)
    float2* __restrict__ out2,        // 2 float2 per tile
    int n4)
{
    unsigned seg = blockIdx.x * (256u * ITERS);
    unsigned tid = threadIdx.x;
    unsigned base = seg + tid;
    unsigned last = (unsigned)n4 - 1u;

    float4 m[ITERS];

    // Front-batch independent loads (MLP_p1 = ITERS); clamp instead of guard.
    #pragma unroll
    for (int k = 0; k < ITERS; k++) {
        unsigned j = base + k * 256u;
        m[k] = __ldcs(&in4[j <= last ? j : last]);
    }

    const unsigned FULL = 0xFFFFFFFFu;
    unsigned r = tid & 3u;
    // Output slot for row r of tile (j>>2): ((j>>2)<<1)|r = (j>>1 & ~1) | r.
    // Hoist the per-thread constant part.
    bool row_ok = r < 2u;

    #pragma unroll
    for (int k = 0; k < ITERS; k++) {
        float x0 = -m[k].y;
        float x1 = -m[k].z;
        float y0 = fmaf(4.0f, m[k].y, -m[k].x) - m[k].z;   // 4b - a - c
        float y1 = fmaf(4.0f, m[k].z, -m[k].y) - m[k].w;   // 4c - b - d

        float z0 = x0 + __shfl_down_sync(FULL, y0, 1);
        float z1 = x1 + __shfl_down_sync(FULL, y1, 1);
        float o0 = z0 + __shfl_down_sync(FULL, x0, 2);
        float o1 = z1 + __shfl_down_sync(FULL, x1, 2);

        unsigned j = base + k * 256u;
        if (row_ok && j <= last) {
            __stcs(&out2[((j >> 2) << 1) | r], make_float2(o0, o1));
        }
    }
}

extern "C" void kernel_launch(void* const* d_in, const int* in_sizes, int n_in,
                              void* d_out, int out_size) {
    const float* x = (const float*)d_in[0];
    float* out = (float*)d_out;
    int n4 = in_sizes[0] / 4;   // number of float4 rows (4 per tile)

    const int threads = 256;
    int rows_per_block = threads * ITERS;
    int blocks = (n4 + rows_per_block - 1) / rows_per_block;
    winograd_kernel<<<blocks, threads>>>(
        (const float4*)x, (float2*)out, n4);
}

// round 16
// speedup vs baseline: 1.0424x; 1.0424x over previous
#include <cuda_runtime.h>

// Winograd F(2x2,3x3) with constant Laplacian filter == direct 3x3 conv of each
// 4x4 tile; row-separable:
//   row r = (a,b,c,d):  x_r = (-b, -c),  y_r = (4b-a-c, 4c-b-d)
//   O_row0 = x_0 + y_1 + x_2 ;  O_row1 = x_1 + y_2 + x_3
//
// One lane per input row (float4, coalesced LDG.128); 4-lane groups assemble a
// tile via SHFL. ITERS=4 independent front-batched loads (MLP=4, regs 32,
// occ ~80%) cover DRAM latency; streaming cache hints (data touched once).
//
// FINAL: this exact config measured 49.9 / 49.6 us wall across two independent
// holds — best replicated result. Kernel is at the HBM streaming ceiling
// (~6.7 TB/s on the 320MB algorithmic-minimum traffic); all structural
// variants (v8 loads, unguarded/clamped paths, deeper MLP, pair-lane shfl)
// measured 51.3-53.2 us. DRAM ~84-86% of spec in every configuration.

#define ITERS 4

__global__ __launch_bounds__(256) void winograd_kernel(
    const float4* __restrict__ in4,   // n4 float4s (4 per tile, row-major)
    float2* __restrict__ out2,        // 2 float2 per tile
    int n4)
{
    // Block owns a contiguous segment of ITERS*256 rows; thread t handles
    // rows seg + t + k*256. lane&3 == row-within-tile for every k.
    int seg = blockIdx.x * (blockDim.x * ITERS);
    int tid = threadIdx.x;

    float4 m[ITERS];
    int    j[ITERS];

    // Front-batch independent loads (MLP_p1 = ITERS)
    #pragma unroll
    for (int k = 0; k < ITERS; k++) {
        j[k] = seg + k * 256 + tid;
        m[k] = (j[k] < n4) ? __ldcs(&in4[j[k]])
                           : make_float4(0.f, 0.f, 0.f, 0.f);
    }

    const unsigned FULL = 0xFFFFFFFFu;
    int r = tid & 3;

    #pragma unroll
    for (int k = 0; k < ITERS; k++) {
        float x0 = -m[k].y;
        float x1 = -m[k].z;
        float y0 = fmaf(4.0f, m[k].y, -m[k].x) - m[k].z;   // 4b - a - c
        float y1 = fmaf(4.0f, m[k].z, -m[k].y) - m[k].w;   // 4c - b - d

        float z0 = x0 + __shfl_down_sync(FULL, y0, 1);
        float z1 = x1 + __shfl_down_sync(FULL, y1, 1);
        float o0 = z0 + __shfl_down_sync(FULL, x0, 2);
        float o1 = z1 + __shfl_down_sync(FULL, x1, 2);

        if (r < 2 && j[k] < n4) {
            // tile = j>>2, output row r of that tile
            __stcs(&out2[((j[k] >> 2) << 1) | r], make_float2(o0, o1));
        }
    }
}

extern "C" void kernel_launch(void* const* d_in, const int* in_sizes, int n_in,
                              void* d_out, int out_size) {
    const float* x = (const float*)d_in[0];
    float* out = (float*)d_out;
    int n4 = in_sizes[0] / 4;   // number of float4 rows (4 per tile)

    const int threads = 256;
    int rows_per_block = threads * ITERS;
    int blocks = (n4 + rows_per_block - 1) / rows_per_block;
    winograd_kernel<<<blocks, threads>>>(
        (const float4*)x, (float2*)out, n4);
}